// round 1
// baseline (speedup 1.0000x reference)
#include <cuda_runtime.h>
#include <stdint.h>

#define D      256
#define MITEMS 16
#define TPB    128
#define RPT    4
#define RPB    (TPB * RPT)   // 512 rows per block
#define QS_STRIDE 520        // padded row stride for transposed q tile
#define NEG_BIG (-1e30f)

// Dynamic smem layout (floats):
//   mem_rm : [0, 4096)            16 x 256 row-major (raw memory, blend source)
//   mem_t  : [4096, 8192)         256 x 16 transposed (dot-phase broadcast, float4-aligned)
//   qs     : [8192, 12352)        8 x 520 transposed q tile [c][row]
//   pw     : [12352, 14400)       512 x 4 softmax weights
//   pidx   : [14400, 14912)       512 packed top-4 indices (int)
#define SMEM_FLOATS 14912
#define SMEM_BYTES  (SMEM_FLOATS * 4)

__global__ void __launch_bounds__(TPB) epm_kernel(
    const float* __restrict__ q,
    const float* __restrict__ mem,
    float* __restrict__ out_ret,
    float* __restrict__ out_max,
    int nrows)
{
    extern __shared__ __align__(16) float sh[];
    float* mem_rm = sh;
    float* mem_t  = sh + 4096;
    float* qs     = sh + 8192;
    float* pw     = sh + 12352;
    int*   pidx   = (int*)(sh + 14400);

    const int tid = threadIdx.x;
    const int blockRow = blockIdx.x * RPB;

    // ---- Load memory bank into smem (both layouts) ----
    #pragma unroll
    for (int i = 0; i < (MITEMS * D) / TPB; i++) {   // 32 iters
        int idx = tid + TPB * i;
        float v = mem[idx];
        mem_rm[idx] = v;
        mem_t[(idx & (D - 1)) * MITEMS + (idx >> 8)] = v;
    }
    // (ordered before first use by the __syncthreads inside the ct loop)

    // ---- Dot phase: register-blocked [4 rows] x [16 items] ----
    float acc[MITEMS][RPT];
    float ssq[RPT];
    #pragma unroll
    for (int m = 0; m < MITEMS; m++)
        #pragma unroll
        for (int r = 0; r < RPT; r++) acc[m][r] = 0.0f;
    #pragma unroll
    for (int r = 0; r < RPT; r++) ssq[r] = 0.0f;

    const int ccw = tid & 7;      // staging column within 8-wide tile
    const int rw0 = tid >> 3;     // staging base row (0..15), step 16

    const int nr1 = nrows - 1;

    for (int ct = 0; ct < D / 8; ct++) {   // 32 column tiles of 8
        __syncthreads();   // protect qs from readers of previous tile
        // stage q[blockRow .. blockRow+511][ct*8 .. ct*8+7] transposed into qs
        #pragma unroll
        for (int i = 0; i < 32; i++) {
            int rl = rw0 + 16 * i;                       // local row 0..511
            int rg = blockRow + rl;
            rg = rg < nr1 ? rg : nr1;                    // clamp (full blocks unaffected)
            qs[ccw * QS_STRIDE + rl] = q[rg * D + ct * 8 + ccw];
        }
        __syncthreads();

        const float* qbase = qs + tid * RPT;
        #pragma unroll
        for (int cc = 0; cc < 8; cc++) {
            int c = ct * 8 + cc;
            float4 q4 = *(const float4*)(qbase + cc * QS_STRIDE);
            const float4* mt = (const float4*)(mem_t + c * MITEMS);
            float4 m0 = mt[0], m1 = mt[1], m2 = mt[2], m3 = mt[3];
            float qv[4] = {q4.x, q4.y, q4.z, q4.w};
            float mv[16] = {m0.x, m0.y, m0.z, m0.w,
                            m1.x, m1.y, m1.z, m1.w,
                            m2.x, m2.y, m2.z, m2.w,
                            m3.x, m3.y, m3.z, m3.w};
            #pragma unroll
            for (int r = 0; r < RPT; r++) ssq[r] += qv[r] * qv[r];
            #pragma unroll
            for (int m = 0; m < MITEMS; m++)
                #pragma unroll
                for (int r = 0; r < RPT; r++)
                    acc[m][r] += mv[m] * qv[r];
        }
    }

    // ---- Per-thread epilogue: normalize, top-4, softmax ----
    #pragma unroll
    for (int r = 0; r < RPT; r++) {
        // sim = dot * (1/|q|) / tau   (memory rows are unit-norm)
        float inv = rsqrtf(fmaxf(ssq[r], 1e-24f)) * 10.0f;
        float s[MITEMS];
        #pragma unroll
        for (int m = 0; m < MITEMS; m++) s[m] = acc[m][r] * inv;

        float bw[4]; int bi[4];
        #pragma unroll
        for (int k = 0; k < 4; k++) {
            float best = NEG_BIG; int b = 0;
            #pragma unroll
            for (int m = 0; m < MITEMS; m++) {
                if (s[m] > best) { best = s[m]; b = m; }
            }
            bw[k] = best; bi[k] = b;
            #pragma unroll
            for (int m = 0; m < MITEMS; m++)
                s[m] = (m == b) ? NEG_BIG : s[m];
        }

        float e0 = 1.0f;
        float e1 = __expf(bw[1] - bw[0]);
        float e2 = __expf(bw[2] - bw[0]);
        float e3 = __expf(bw[3] - bw[0]);
        float rden = 1.0f / (e0 + e1 + e2 + e3);

        int row_l = tid * RPT + r;
        int row_g = blockRow + row_l;
        pw[row_l * 4 + 0] = e0 * rden;
        pw[row_l * 4 + 1] = e1 * rden;
        pw[row_l * 4 + 2] = e2 * rden;
        pw[row_l * 4 + 3] = e3 * rden;
        pidx[row_l] = bi[0] | (bi[1] << 4) | (bi[2] << 8) | (bi[3] << 12);
        if (row_g < nrows) out_max[row_g] = bw[0];
    }
    __syncthreads();

    // ---- Blend phase: warp-per-row (lanes share idx -> conflict-free LDS.128) ----
    const int wid  = tid >> 5;
    const int lane = tid & 31;
    #pragma unroll 2
    for (int i = 0; i < RPB / 4; i++) {      // 128 rows per warp
        int row_l = wid * (RPB / 4) + i;
        int row_g = blockRow + row_l;
        float4 w4 = *(const float4*)(pw + row_l * 4);
        int pk = pidx[row_l];
        const float4* b0 = (const float4*)(mem_rm + ((pk      ) & 15) * D);
        const float4* b1 = (const float4*)(mem_rm + ((pk >> 4 ) & 15) * D);
        const float4* b2 = (const float4*)(mem_rm + ((pk >> 8 ) & 15) * D);
        const float4* b3 = (const float4*)(mem_rm + ((pk >> 12) & 15) * D);
        float4* orow = (float4*)(out_ret + (size_t)row_g * D);
        bool ok = row_g < nrows;
        #pragma unroll
        for (int t = 0; t < 2; t++) {
            int c4 = lane + 32 * t;          // float4 column index 0..63
            float4 a0 = b0[c4], a1 = b1[c4], a2 = b2[c4], a3 = b3[c4];
            float4 o;
            o.x = w4.x * a0.x + w4.y * a1.x + w4.z * a2.x + w4.w * a3.x;
            o.y = w4.x * a0.y + w4.y * a1.y + w4.z * a2.y + w4.w * a3.y;
            o.z = w4.x * a0.z + w4.y * a1.z + w4.z * a2.z + w4.w * a3.z;
            o.w = w4.x * a0.w + w4.y * a1.w + w4.z * a2.w + w4.w * a3.w;
            if (ok) orow[c4] = o;
        }
    }
}

extern "C" void kernel_launch(void* const* d_in, const int* in_sizes, int n_in,
                              void* d_out, int out_size)
{
    const float* q   = (const float*)d_in[0];
    const float* mem = (const float*)d_in[1];
    int nrows = in_sizes[0] / D;              // 131072
    float* out_ret = (float*)d_out;
    float* out_max = out_ret + (size_t)nrows * D;

    cudaFuncSetAttribute(epm_kernel,
                         cudaFuncAttributeMaxDynamicSharedMemorySize, SMEM_BYTES);

    int grid = (nrows + RPB - 1) / RPB;       // 256
    epm_kernel<<<grid, TPB, SMEM_BYTES>>>(q, mem, out_ret, out_max, nrows);
}